// round 16
// baseline (speedup 1.0000x reference)
#include <cuda_runtime.h>
#include <cuda_fp16.h>
#include <cstdint>
#include <math.h>

#define BB 4
#define NN 2048
#define DIMM 512
#define TT 16
#define HH 8
#define DHH 64
#define ROWS (BB*NN)          // 8192
#define QKVN (3*HH*DHH)       // 1536
#define HDSZ (BB*HH*NN*DHH)
#define KDIM 512              // GEMM K dim (both GEMMs), 8 chunks of 64

typedef __half f16;

// ---------------- scratch (static device globals) ----------------
__device__ f16 g_xn[ROWS*DIMM];                      // layernorm out fp16
__device__ f16 g_wq[QKVN*DIMM];                      // W_qkv^T fp16
__device__ f16 g_wo[DIMM*DIMM];                      // W_out^T fp16
__device__ f16 g_q[HDSZ], g_k[HDSZ], g_v[HDSZ];      // Q,K,V fp16
__device__ f16 g_a[ROWS*DIMM];                       // attention out fp16

// ---------------- helpers ----------------
__device__ __forceinline__ uint32_t swz(uint32_t o) { return o ^ ((o >> 3) & 0x70u); }

__device__ __forceinline__ uint32_t smem_u32(const void* p) {
    uint32_t a;
    asm("{ .reg .u64 t; cvta.to.shared.u64 t, %1; cvt.u32.u64 %0, t; }" : "=r"(a) : "l"(p));
    return a;
}

__device__ __forceinline__ uint32_t pack2h(float lo, float hi) {
    uint32_t r;
    asm("cvt.rn.f16x2.f32 %0, %1, %2;" : "=r"(r) : "f"(hi), "f"(lo));
    return r;
}
__device__ __forceinline__ float ex2f(float x) {
    float y;
    asm("ex2.approx.f32 %0, %1;" : "=f"(y) : "f"(x));
    return y;
}

__device__ __forceinline__ void ldsm_x4(uint32_t* r, uint32_t addr) {
    asm volatile("ldmatrix.sync.aligned.m8n8.x4.shared.b16 {%0,%1,%2,%3}, [%4];"
        : "=r"(r[0]), "=r"(r[1]), "=r"(r[2]), "=r"(r[3]) : "r"(addr));
}
__device__ __forceinline__ void ldsm_x4t(uint32_t* r, uint32_t addr) {
    asm volatile("ldmatrix.sync.aligned.m8n8.x4.trans.shared.b16 {%0,%1,%2,%3}, [%4];"
        : "=r"(r[0]), "=r"(r[1]), "=r"(r[2]), "=r"(r[3]) : "r"(addr));
}
__device__ __forceinline__ void mma16816(float* c, const uint32_t* a, const uint32_t* b) {
    asm volatile("mma.sync.aligned.m16n8k16.row.col.f32.f16.f16.f32 "
        "{%0,%1,%2,%3}, {%4,%5,%6,%7}, {%8,%9}, {%0,%1,%2,%3};"
        : "+f"(c[0]), "+f"(c[1]), "+f"(c[2]), "+f"(c[3])
        : "r"(a[0]), "r"(a[1]), "r"(a[2]), "r"(a[3]), "r"(b[0]), "r"(b[1]));
}
__device__ __forceinline__ void cp16(uint32_t dst, const void* src) {
    asm volatile("cp.async.cg.shared.global [%0], [%1], 16;" :: "r"(dst), "l"(src) : "memory");
}
#define CP_COMMIT() asm volatile("cp.async.commit_group;" ::: "memory")
#define CP_WAIT1()  asm volatile("cp.async.wait_group 1;" ::: "memory")
#define CP_WAIT0()  asm volatile("cp.async.wait_group 0;" ::: "memory")

// ---------------- fused prep: warp-per-row LN + weight transposes ----------------
#define LN_BLOCKS (ROWS / 8)

__global__ void __launch_bounds__(256) prep_kernel(const float* __restrict__ x,
                                                   const float* __restrict__ gamma,
                                                   const float* __restrict__ beta,
                                                   const float* __restrict__ Wqkv,
                                                   const float* __restrict__ Wout,
                                                   f16* __restrict__ xn)
{
    int blk = blockIdx.x;
    int t = threadIdx.x;
    int lane = t & 31, wid = t >> 5;

    if (blk < LN_BLOCKS) {
        int row = blk * 8 + wid;
        const float4* xr = (const float4*)(x + (size_t)row * DIMM);
        float4 v[4];
        float s = 0.f, ss = 0.f;
        #pragma unroll
        for (int j = 0; j < 4; j++) {
            v[j] = xr[lane + 32 * j];
            s  += v[j].x + v[j].y + v[j].z + v[j].w;
            ss += v[j].x*v[j].x + v[j].y*v[j].y + v[j].z*v[j].z + v[j].w*v[j].w;
        }
        #pragma unroll
        for (int o = 16; o > 0; o >>= 1) {
            s  += __shfl_xor_sync(0xffffffffu, s,  o);
            ss += __shfl_xor_sync(0xffffffffu, ss, o);
        }
        float mu  = s * (1.0f / DIMM);
        float var = ss * (1.0f / DIMM) - mu * mu;
        float inv = rsqrtf(var + 1e-5f);
        uint2* dst = (uint2*)(xn + (size_t)row * DIMM);
        #pragma unroll
        for (int j = 0; j < 4; j++) {
            float4 g = ((const float4*)gamma)[lane + 32 * j];
            float4 be = ((const float4*)beta)[lane + 32 * j];
            float o0 = (v[j].x - mu) * inv * g.x + be.x;
            float o1 = (v[j].y - mu) * inv * g.y + be.y;
            float o2 = (v[j].z - mu) * inv * g.z + be.z;
            float o3 = (v[j].w - mu) * inv * g.w + be.w;
            uint2 pkd;
            pkd.x = pack2h(o0, o1);
            pkd.y = pack2h(o2, o3);
            dst[lane + 32 * j] = pkd;
        }
    } else {
        __shared__ float tsh[32 * 33];
        const float* W;
        f16* dst;
        int Nd, Kd, idx;
        if (blk < LN_BLOCKS + (QKVN / 32) * (DIMM / 32)) {
            idx = blk - LN_BLOCKS;
            W = Wqkv; dst = g_wq; Nd = QKVN; Kd = DIMM;
        } else {
            idx = blk - LN_BLOCKS - (QKVN / 32) * (DIMM / 32);
            W = Wout; dst = g_wo; Nd = DIMM; Kd = DIMM;
        }
        int nblk = Nd / 32;
        int n0 = (idx % nblk) * 32, k0 = (idx / nblk) * 32;
        int tx = t & 31, ty = t >> 5;
        #pragma unroll
        for (int i = 0; i < 4; i++)
            tsh[(ty + 8 * i) * 33 + tx] = W[(size_t)(k0 + ty + 8 * i) * Nd + n0 + tx];
        __syncthreads();
        #pragma unroll
        for (int i = 0; i < 4; i++) {
            int n = n0 + ty + 8 * i, k = k0 + tx;
            dst[(size_t)n * Kd + k] = __float2half(tsh[tx * 33 + ty + 8 * i]);
        }
    }
}

// ---------------- persistent HMMA GEMM: C[M,N] = A[M,512] @ B[N,512]^T ----------------
// CTA 128x128 tiles, persistent loop; cp.async ring continues ACROSS tiles,
// so tile t's epilogue covers tile t+1's chunk 0/1 fill. K = 512 fixed (8 chunks).
#define GA 0
#define GB 16384
#define GSTAGE 32768
#define GEMM_SMEM (2*GSTAGE)   // 65536

template<bool SCATTER>
__global__ void __launch_bounds__(256, 2)
mma_gemm(const f16* __restrict__ A, const f16* __restrict__ B,
         float* __restrict__ C, int Ncols, int ntiles, int nx,
         f16* qo, f16* ko, f16* vo)
{
    extern __shared__ char smc[];
    uint32_t sb = smem_u32(smc);
    int tid = threadIdx.x, lane = tid & 31, wid = tid >> 5;
    int m0w = (wid >> 2) * 64, n0w = (wid & 3) * 32;

    auto load_chunk_at = [&](int tidx_l, int kc, int st) {
        int n0l = (tidx_l % nx) * 128, m0l = (tidx_l / nx) * 128;
        const f16* sA = A + (size_t)m0l * KDIM + kc * 64;
        const f16* sB = B + (size_t)n0l * KDIM + kc * 64;
        uint32_t base = sb + st * GSTAGE;
        #pragma unroll
        for (int i = 0; i < 4; i++) {
            int u = tid + i * 256;
            int row = u >> 3, g = u & 7;
            cp16(base + GA + swz(row * 128 + g * 16),
                 sA + (size_t)row * KDIM + g * 8);
        }
        #pragma unroll
        for (int i = 0; i < 4; i++) {
            int u = tid + i * 256;
            int row = u >> 3, g = u & 7;
            cp16(base + GB + swz(row * 128 + g * 16),
                 sB + (size_t)row * KDIM + g * 8);
        }
        CP_COMMIT();
    };

    // load iterator (tile, chunk) — strided tile walk
    int load_tidx = blockIdx.x, load_kc = 0;

    load_chunk_at(load_tidx, load_kc, 0);
    if (++load_kc == 8) { load_kc = 0; load_tidx += gridDim.x; }
    if (load_tidx < ntiles) {
        load_chunk_at(load_tidx, load_kc, 1);
        if (++load_kc == 8) { load_kc = 0; load_tidx += gridDim.x; }
    }

    int stage = 0;
    for (int tidx = blockIdx.x; tidx < ntiles; tidx += gridDim.x) {
        int n0 = (tidx % nx) * 128, m0 = (tidx / nx) * 128;

        float acc[4][4][4];
        #pragma unroll
        for (int a = 0; a < 4; a++)
            #pragma unroll
            for (int b = 0; b < 4; b++)
                #pragma unroll
                for (int c = 0; c < 4; c++) acc[a][b][c] = 0.f;

        for (int kc = 0; kc < 8; kc++) {
            bool more = (load_tidx < ntiles);
            if (more) { CP_WAIT1(); } else { CP_WAIT0(); }
            __syncthreads();
            uint32_t bs = sb + stage * GSTAGE;
            #pragma unroll
            for (int kt = 0; kt < 4; kt++) {
                uint32_t af[4][4];
                #pragma unroll
                for (int mt = 0; mt < 4; mt++) {
                    uint32_t byte = swz((m0w + mt * 16 + (lane & 15)) * 128 +
                                        kt * 32 + (lane >> 4) * 16);
                    ldsm_x4(af[mt], bs + GA + byte);
                }
                #pragma unroll
                for (int p = 0; p < 2; p++) {
                    uint32_t byte = swz((n0w + p * 16 + (lane & 7) + ((lane >> 4) << 3)) * 128 +
                                        kt * 32 + ((lane >> 3) & 1) * 16);
                    uint32_t bf[4];
                    ldsm_x4(bf, bs + GB + byte);
                    #pragma unroll
                    for (int mt = 0; mt < 4; mt++)
                        #pragma unroll
                        for (int half = 0; half < 2; half++) {
                            int nt = p * 2 + half;
                            mma16816(acc[mt][nt], af[mt], &bf[half * 2]);
                        }
                }
            }
            __syncthreads();
            if (more) {
                load_chunk_at(load_tidx, load_kc, stage);
                if (++load_kc == 8) { load_kc = 0; load_tidx += gridDim.x; }
            }
            stage ^= 1;
        }

        // epilogue (overlaps next tile's in-flight chunk 0/1 loads)
        int rbase = m0 + m0w + (lane >> 2);
        int cbase = n0 + n0w + 2 * (lane & 3);
        #pragma unroll
        for (int mt = 0; mt < 4; mt++) {
            #pragma unroll
            for (int nt = 0; nt < 4; nt++) {
                #pragma unroll
                for (int half = 0; half < 2; half++) {
                    int r = rbase + mt * 16 + half * 8;
                    int cc = cbase + nt * 8;
                    float f0 = acc[mt][nt][half * 2], f1 = acc[mt][nt][half * 2 + 1];
                    if (SCATTER) {
                        uint32_t hp = pack2h(f0, f1);
                        int b = r >> 11, n = r & 2047;
                        int part = cc >> 9, h = (cc >> 6) & 7, d = cc & 63;
                        size_t idx = (((size_t)(b * HH + h)) * NN + n) * DHH + d;
                        f16* dst = (part == 0) ? qo : ((part == 1) ? ko : vo);
                        *(uint32_t*)(dst + idx) = hp;
                    } else {
                        float2 o2; o2.x = f0; o2.y = f1;
                        *(float2*)(C + (size_t)r * Ncols + cc) = o2;
                    }
                }
            }
        }
    }
}

// ---------------- HMMA flash attention (fp16, 4 warps x 32 q-rows) ----------------
// R15: 64-row KV tiles, 3-stage single-sync ring, smem 64KB, 2 CTAs/SM.
#define FQ 0
#define FKV 16384
#define FSTAGE 16384
#define FLASH_SMEM (FKV + 3*FSTAGE)   // 65536

__global__ void __launch_bounds__(128, 2)
flash_mma(const f16* __restrict__ qq, const f16* __restrict__ kk,
          const f16* __restrict__ vv,
          const float* __restrict__ Rg,
          const float* __restrict__ avec, const float* __restrict__ cvec,
          f16* __restrict__ aout)
{
    extern __shared__ char smc[];
    uint32_t sb = smem_u32(smc);
    int tid = threadIdx.x, lane = tid & 31, wid = tid >> 5;
    int bid = blockIdx.x;
    int qt = bid & 15, h = (bid >> 4) & 7, b = bid >> 7;
    int bh = b * HH + h;

    float aa = fabsf(avec[h]);
    float ca = fabsf(cvec[h]);

    auto load_kv = [&](int jt, int st) {
        size_t o = ((size_t)bh * NN + jt * 64) * DHH;
        const f16* s2[2] = {kk + o, vv + o};
        uint32_t base = sb + FKV + st * FSTAGE;
        #pragma unroll
        for (int t = 0; t < 2; t++) {
            #pragma unroll
            for (int i = 0; i < 4; i++) {
                int u = tid + i * 128;
                int row = u >> 3, g = u & 7;
                cp16(base + t * 8192 + swz(row * 128 + g * 16),
                     s2[t] + (size_t)row * DHH + g * 8);
            }
        }
        CP_COMMIT();
    };

    {
        size_t qo = ((size_t)bh * NN + qt * 128) * DHH;
        #pragma unroll
        for (int i = 0; i < 8; i++) {
            int u = tid + i * 128;
            int row = u >> 3, g = u & 7;
            cp16(sb + FQ + swz(row * 128 + g * 16),
                 qq + qo + (size_t)row * DHH + g * 8);
        }
    }
    load_kv(0, 0);
    load_kv(1, 1);

    CP_WAIT1();
    __syncthreads();

    uint32_t qa[4][2][4];
    #pragma unroll
    for (int kt = 0; kt < 4; kt++)
        #pragma unroll
        for (int mt = 0; mt < 2; mt++) {
            uint32_t abyte = swz((wid * 32 + mt * 16 + (lane & 15)) * 128 +
                                 kt * 32 + (lane >> 4) * 16);
            ldsm_x4(qa[kt][mt], sb + FQ + abyte);
        }

    float oacc[2][8][4];
    #pragma unroll
    for (int mt = 0; mt < 2; mt++)
        #pragma unroll
        for (int i = 0; i < 8; i++)
            #pragma unroll
            for (int j = 0; j < 4; j++) oacc[mt][i][j] = 0.f;
    float rsum[2][2] = {{0.f, 0.f}, {0.f, 0.f}};

    for (int jt = 0; jt < 32; jt++) {
        if (jt + 1 < 32) { CP_WAIT1(); } else { CP_WAIT0(); }
        __syncthreads();
        if (jt + 2 < 32) load_kv(jt + 2, (jt + 2) % 3);

        uint32_t bK = sb + FKV + (jt % 3) * FSTAGE;
        uint32_t bV = bK + 8192;

        float rb = Rg[((size_t)b * TT + qt) * TT + (jt >> 1)];
        float dscale = (1.f / (1.f + __expf(aa * rb - ca))) * 0.125f * 1.44269504f;

        #pragma unroll
        for (int c = 0; c < 2; c++) {
            float sacc[2][4][4];
            #pragma unroll
            for (int mt = 0; mt < 2; mt++)
                #pragma unroll
                for (int i = 0; i < 4; i++)
                    #pragma unroll
                    for (int j = 0; j < 4; j++) sacc[mt][i][j] = 0.f;

            #pragma unroll
            for (int kt = 0; kt < 4; kt++) {
                #pragma unroll
                for (int p = 0; p < 2; p++) {
                    int p16 = c * 2 + p;
                    uint32_t bbyte = swz((p16 * 16 + (lane & 7) + ((lane >> 4) << 3)) * 128 +
                                         kt * 32 + ((lane >> 3) & 1) * 16);
                    uint32_t kb[4];
                    ldsm_x4(kb, bK + bbyte);
                    #pragma unroll
                    for (int mt = 0; mt < 2; mt++)
                        #pragma unroll
                        for (int half = 0; half < 2; half++)
                            mma16816(sacc[mt][p * 2 + half], qa[kt][mt], &kb[half * 2]);
                }
            }

            #pragma unroll
            for (int mt = 0; mt < 2; mt++)
                #pragma unroll
                for (int nt = 0; nt < 4; nt++)
                    #pragma unroll
                    for (int r = 0; r < 4; r++) {
                        float p = ex2f(fmaxf(sacc[mt][nt][r], 0.f) * dscale);
                        sacc[mt][nt][r] = p;
                        rsum[mt][r >> 1] += p;
                    }

            uint32_t pa[2][2][4];
            #pragma unroll
            for (int mt = 0; mt < 2; mt++)
                #pragma unroll
                for (int g = 0; g < 2; g++) {
                    pa[mt][g][0] = pack2h(sacc[mt][2*g][0],   sacc[mt][2*g][1]);
                    pa[mt][g][1] = pack2h(sacc[mt][2*g][2],   sacc[mt][2*g][3]);
                    pa[mt][g][2] = pack2h(sacc[mt][2*g+1][0], sacc[mt][2*g+1][1]);
                    pa[mt][g][3] = pack2h(sacc[mt][2*g+1][2], sacc[mt][2*g+1][3]);
                }

            #pragma unroll
            for (int g = 0; g < 2; g++) {
                int vrow = c * 32 + g * 16;
                #pragma unroll
                for (int p = 0; p < 4; p++) {
                    uint32_t vbyte = swz((vrow + (lane & 7) + ((lane >> 3) & 1) * 8) * 128 +
                                         p * 32 + (lane >> 4) * 16);
                    uint32_t vb[4];
                    ldsm_x4t(vb, bV + vbyte);
                    #pragma unroll
                    for (int mt = 0; mt < 2; mt++)
                        #pragma unroll
                        for (int half = 0; half < 2; half++)
                            mma16816(oacc[mt][p * 2 + half], pa[mt][g], &vb[half * 2]);
                }
            }
        }
    }

    #pragma unroll
    for (int mt = 0; mt < 2; mt++)
        #pragma unroll
        for (int hh = 0; hh < 2; hh++) {
            rsum[mt][hh] += __shfl_xor_sync(0xffffffffu, rsum[mt][hh], 1);
            rsum[mt][hh] += __shfl_xor_sync(0xffffffffu, rsum[mt][hh], 2);
        }

    int r0 = qt * 128 + wid * 32 + (lane >> 2);
    f16* ob = aout + ((size_t)b * NN + r0) * DIMM + h * DHH;
    #pragma unroll
    for (int mt = 0; mt < 2; mt++) {
        float inv_lo = 1.f / rsum[mt][0], inv_hi = 1.f / rsum[mt][1];
        f16* om = ob + (size_t)(mt * 16) * DIMM;
        #pragma unroll
        for (int nt = 0; nt < 8; nt++) {
            int c = nt * 8 + 2 * (lane & 3);
            *(uint32_t*)(om + c) =
                pack2h(oacc[mt][nt][0] * inv_lo, oacc[mt][nt][1] * inv_lo);
            *(uint32_t*)(om + (size_t)8 * DIMM + c) =
                pack2h(oacc[mt][nt][2] * inv_hi, oacc[mt][nt][3] * inv_hi);
        }
    }
}

// ---------------- launch ----------------
extern "C" void kernel_launch(void* const* d_in, const int* in_sizes, int n_in,
                              void* d_out, int out_size)
{
    const float* x     = (const float*)d_in[0];
    const float* R     = (const float*)d_in[1];
    const float* gamma = (const float*)d_in[2];
    const float* beta  = (const float*)d_in[3];
    const float* Wqkv  = (const float*)d_in[4];
    const float* Wout  = (const float*)d_in[5];
    const float* av    = (const float*)d_in[6];
    const float* cv    = (const float*)d_in[7];
    float* out = (float*)d_out;

    f16 *xn, *wq, *wo, *qq, *kk, *vv, *aa;
    cudaGetSymbolAddress((void**)&xn, g_xn);
    cudaGetSymbolAddress((void**)&wq, g_wq);   cudaGetSymbolAddress((void**)&wo, g_wo);
    cudaGetSymbolAddress((void**)&qq, g_q);    cudaGetSymbolAddress((void**)&kk, g_k);
    cudaGetSymbolAddress((void**)&vv, g_v);    cudaGetSymbolAddress((void**)&aa, g_a);

    cudaFuncSetAttribute((const void*)mma_gemm<true>,
                         cudaFuncAttributeMaxDynamicSharedMemorySize, GEMM_SMEM);
    cudaFuncSetAttribute((const void*)mma_gemm<false>,
                         cudaFuncAttributeMaxDynamicSharedMemorySize, GEMM_SMEM);
    cudaFuncSetAttribute((const void*)flash_mma,
                         cudaFuncAttributeMaxDynamicSharedMemorySize, FLASH_SMEM);

    // 1) fused prep: warp-per-row LN + weight transposes
    int prep_blocks = LN_BLOCKS + (QKVN / 32) * (DIMM / 32) + (DIMM / 32) * (DIMM / 32);
    prep_kernel<<<prep_blocks, 256>>>(x, gamma, beta, Wqkv, Wout, xn);

    // 2) QKV projection: 768 tiles, persistent grid 296 (2 CTAs/SM)
    {
        int ntiles = (QKVN / 128) * (ROWS / 128);   // 768
        int nx = QKVN / 128;                        // 12
        mma_gemm<true><<<296, 256, GEMM_SMEM>>>(
            xn, wq, nullptr, QKVN, ntiles, nx, qq, kk, vv);
    }

    // 3) flash attention (64-row KV tiles, 3-stage single-sync ring)
    flash_mma<<<BB * HH * 16, 128, FLASH_SMEM>>>(qq, kk, vv, R, av, cv, aa);

    // 4) output projection: 256 tiles, grid 256
    {
        int ntiles = (DIMM / 128) * (ROWS / 128);   // 256
        int nx = DIMM / 128;                        // 4
        mma_gemm<false><<<256, 256, GEMM_SMEM>>>(
            aa, wo, out, DIMM, ntiles, nx, nullptr, nullptr, nullptr);
    }
}

// round 17
// speedup vs baseline: 1.0268x; 1.0268x over previous
#include <cuda_runtime.h>
#include <cuda_fp16.h>
#include <cstdint>
#include <math.h>

#define BB 4
#define NN 2048
#define DIMM 512
#define TT 16
#define HH 8
#define DHH 64
#define ROWS (BB*NN)          // 8192
#define QKVN (3*HH*DHH)       // 1536
#define HDSZ (BB*HH*NN*DHH)

typedef __half f16;

// ---------------- scratch (static device globals) ----------------
__device__ f16 g_xn[ROWS*DIMM];                      // layernorm out fp16
__device__ f16 g_wq[QKVN*DIMM];                      // W_qkv^T fp16
__device__ f16 g_wo[DIMM*DIMM];                      // W_out^T fp16
__device__ f16 g_q[HDSZ], g_k[HDSZ], g_v[HDSZ];      // Q,K,V fp16
__device__ f16 g_a[ROWS*DIMM];                       // attention out fp16

// ---------------- helpers ----------------
__device__ __forceinline__ uint32_t swz(uint32_t o) { return o ^ ((o >> 3) & 0x70u); }

__device__ __forceinline__ uint32_t smem_u32(const void* p) {
    uint32_t a;
    asm("{ .reg .u64 t; cvta.to.shared.u64 t, %1; cvt.u32.u64 %0, t; }" : "=r"(a) : "l"(p));
    return a;
}

__device__ __forceinline__ uint32_t pack2h(float lo, float hi) {
    uint32_t r;
    asm("cvt.rn.f16x2.f32 %0, %1, %2;" : "=r"(r) : "f"(hi), "f"(lo));
    return r;
}
__device__ __forceinline__ float ex2f(float x) {
    float y;
    asm("ex2.approx.f32 %0, %1;" : "=f"(y) : "f"(x));
    return y;
}

__device__ __forceinline__ void ldsm_x4(uint32_t* r, uint32_t addr) {
    asm volatile("ldmatrix.sync.aligned.m8n8.x4.shared.b16 {%0,%1,%2,%3}, [%4];"
        : "=r"(r[0]), "=r"(r[1]), "=r"(r[2]), "=r"(r[3]) : "r"(addr));
}
__device__ __forceinline__ void ldsm_x4t(uint32_t* r, uint32_t addr) {
    asm volatile("ldmatrix.sync.aligned.m8n8.x4.trans.shared.b16 {%0,%1,%2,%3}, [%4];"
        : "=r"(r[0]), "=r"(r[1]), "=r"(r[2]), "=r"(r[3]) : "r"(addr));
}
__device__ __forceinline__ void mma16816(float* c, const uint32_t* a, const uint32_t* b) {
    asm volatile("mma.sync.aligned.m16n8k16.row.col.f32.f16.f16.f32 "
        "{%0,%1,%2,%3}, {%4,%5,%6,%7}, {%8,%9}, {%0,%1,%2,%3};"
        : "+f"(c[0]), "+f"(c[1]), "+f"(c[2]), "+f"(c[3])
        : "r"(a[0]), "r"(a[1]), "r"(a[2]), "r"(a[3]), "r"(b[0]), "r"(b[1]));
}
__device__ __forceinline__ void cp16(uint32_t dst, const void* src) {
    asm volatile("cp.async.cg.shared.global [%0], [%1], 16;" :: "r"(dst), "l"(src) : "memory");
}
#define CP_COMMIT() asm volatile("cp.async.commit_group;" ::: "memory")
#define CP_WAIT1()  asm volatile("cp.async.wait_group 1;" ::: "memory")
#define CP_WAIT0()  asm volatile("cp.async.wait_group 0;" ::: "memory")

// ---------------- fused prep: warp-per-row LN + weight transposes ----------------
#define LN_BLOCKS (ROWS / 8)

__global__ void __launch_bounds__(256) prep_kernel(const float* __restrict__ x,
                                                   const float* __restrict__ gamma,
                                                   const float* __restrict__ beta,
                                                   const float* __restrict__ Wqkv,
                                                   const float* __restrict__ Wout,
                                                   f16* __restrict__ xn)
{
    int blk = blockIdx.x;
    int t = threadIdx.x;
    int lane = t & 31, wid = t >> 5;

    if (blk < LN_BLOCKS) {
        int row = blk * 8 + wid;
        const float4* xr = (const float4*)(x + (size_t)row * DIMM);
        float4 v[4];
        float s = 0.f, ss = 0.f;
        #pragma unroll
        for (int j = 0; j < 4; j++) {
            v[j] = xr[lane + 32 * j];
            s  += v[j].x + v[j].y + v[j].z + v[j].w;
            ss += v[j].x*v[j].x + v[j].y*v[j].y + v[j].z*v[j].z + v[j].w*v[j].w;
        }
        #pragma unroll
        for (int o = 16; o > 0; o >>= 1) {
            s  += __shfl_xor_sync(0xffffffffu, s,  o);
            ss += __shfl_xor_sync(0xffffffffu, ss, o);
        }
        float mu  = s * (1.0f / DIMM);
        float var = ss * (1.0f / DIMM) - mu * mu;
        float inv = rsqrtf(var + 1e-5f);
        uint2* dst = (uint2*)(xn + (size_t)row * DIMM);
        #pragma unroll
        for (int j = 0; j < 4; j++) {
            float4 g = ((const float4*)gamma)[lane + 32 * j];
            float4 be = ((const float4*)beta)[lane + 32 * j];
            float o0 = (v[j].x - mu) * inv * g.x + be.x;
            float o1 = (v[j].y - mu) * inv * g.y + be.y;
            float o2 = (v[j].z - mu) * inv * g.z + be.z;
            float o3 = (v[j].w - mu) * inv * g.w + be.w;
            uint2 pkd;
            pkd.x = pack2h(o0, o1);
            pkd.y = pack2h(o2, o3);
            dst[lane + 32 * j] = pkd;
        }
    } else {
        __shared__ float tsh[32 * 33];
        const float* W;
        f16* dst;
        int Nd, Kd, idx;
        if (blk < LN_BLOCKS + (QKVN / 32) * (DIMM / 32)) {
            idx = blk - LN_BLOCKS;
            W = Wqkv; dst = g_wq; Nd = QKVN; Kd = DIMM;
        } else {
            idx = blk - LN_BLOCKS - (QKVN / 32) * (DIMM / 32);
            W = Wout; dst = g_wo; Nd = DIMM; Kd = DIMM;
        }
        int nblk = Nd / 32;
        int n0 = (idx % nblk) * 32, k0 = (idx / nblk) * 32;
        int tx = t & 31, ty = t >> 5;
        #pragma unroll
        for (int i = 0; i < 4; i++)
            tsh[(ty + 8 * i) * 33 + tx] = W[(size_t)(k0 + ty + 8 * i) * Nd + n0 + tx];
        __syncthreads();
        #pragma unroll
        for (int i = 0; i < 4; i++) {
            int n = n0 + ty + 8 * i, k = k0 + tx;
            dst[(size_t)n * Kd + k] = __float2half(tsh[tx * 33 + ty + 8 * i]);
        }
    }
}

// ---------------- HMMA GEMM: C[M,N] = A[M,K] @ B[N,K]^T (1-term fp16) ----------------
// CTA 128x128, 8 warps (2x4, warp tile 64x32), K chunk 64,
// 2-stage cp.async; stage 32KB; 2 CTAs/SM; ~128 regs.
#define GA 0
#define GB 16384
#define GSTAGE 32768
#define GEMM_SMEM (2*GSTAGE)   // 65536

template<bool SCATTER>
__global__ void __launch_bounds__(256, 2)
mma_gemm(const f16* __restrict__ A, const f16* __restrict__ B,
         float* __restrict__ C, int Ncols, int K,
         f16* qo, f16* ko, f16* vo)
{
    extern __shared__ char smc[];
    uint32_t sb = smem_u32(smc);
    int tid = threadIdx.x, lane = tid & 31, wid = tid >> 5;
    int n0 = blockIdx.x * 128, m0 = blockIdx.y * 128;
    int m0w = (wid >> 2) * 64, n0w = (wid & 3) * 32;

    const f16* srcA = A + (size_t)m0 * K;
    const f16* srcB = B + (size_t)n0 * K;

    auto load_chunk = [&](int kc, int st) {
        uint32_t base = sb + st * GSTAGE;
        int kofs = kc * 64;
        #pragma unroll
        for (int i = 0; i < 4; i++) {
            int u = tid + i * 256;
            int row = u >> 3, g = u & 7;
            cp16(base + GA + swz(row * 128 + g * 16),
                 srcA + (size_t)row * K + kofs + g * 8);
        }
        #pragma unroll
        for (int i = 0; i < 4; i++) {
            int u = tid + i * 256;
            int row = u >> 3, g = u & 7;
            cp16(base + GB + swz(row * 128 + g * 16),
                 srcB + (size_t)row * K + kofs + g * 8);
        }
        CP_COMMIT();
    };

    float acc[4][4][4];
    #pragma unroll
    for (int a = 0; a < 4; a++)
        #pragma unroll
        for (int b = 0; b < 4; b++)
            #pragma unroll
            for (int c = 0; c < 4; c++) acc[a][b][c] = 0.f;

    int nch = K >> 6;
    load_chunk(0, 0);
    if (nch > 1) load_chunk(1, 1);
    for (int kc = 0; kc < nch; kc++) {
        if (kc + 1 < nch) { CP_WAIT1(); } else { CP_WAIT0(); }
        __syncthreads();
        uint32_t bs = sb + (kc & 1) * GSTAGE;
        #pragma unroll
        for (int kt = 0; kt < 4; kt++) {
            uint32_t af[4][4];
            #pragma unroll
            for (int mt = 0; mt < 4; mt++) {
                uint32_t byte = swz((m0w + mt * 16 + (lane & 15)) * 128 +
                                    kt * 32 + (lane >> 4) * 16);
                ldsm_x4(af[mt], bs + GA + byte);
            }
            #pragma unroll
            for (int p = 0; p < 2; p++) {
                uint32_t byte = swz((n0w + p * 16 + (lane & 7) + ((lane >> 4) << 3)) * 128 +
                                    kt * 32 + ((lane >> 3) & 1) * 16);
                uint32_t bf[4];
                ldsm_x4(bf, bs + GB + byte);
                #pragma unroll
                for (int mt = 0; mt < 4; mt++)
                    #pragma unroll
                    for (int half = 0; half < 2; half++) {
                        int nt = p * 2 + half;
                        mma16816(acc[mt][nt], af[mt], &bf[half * 2]);
                    }
            }
        }
        __syncthreads();
        if (kc + 2 < nch) load_chunk(kc + 2, kc & 1);
    }

    // epilogue
    int rbase = m0 + m0w + (lane >> 2);
    int cbase = n0 + n0w + 2 * (lane & 3);
    #pragma unroll
    for (int mt = 0; mt < 4; mt++) {
        #pragma unroll
        for (int nt = 0; nt < 4; nt++) {
            #pragma unroll
            for (int half = 0; half < 2; half++) {
                int r = rbase + mt * 16 + half * 8;
                int cc = cbase + nt * 8;
                float f0 = acc[mt][nt][half * 2], f1 = acc[mt][nt][half * 2 + 1];
                if (SCATTER) {
                    uint32_t hp = pack2h(f0, f1);
                    int b = r >> 11, n = r & 2047;
                    int part = cc >> 9, h = (cc >> 6) & 7, d = cc & 63;
                    size_t idx = (((size_t)(b * HH + h)) * NN + n) * DHH + d;
                    f16* dst = (part == 0) ? qo : ((part == 1) ? ko : vo);
                    *(uint32_t*)(dst + idx) = hp;
                } else {
                    float2 o2; o2.x = f0; o2.y = f1;
                    *(float2*)(C + (size_t)r * Ncols + cc) = o2;
                }
            }
        }
    }
}

// ---------------- HMMA flash attention (fp16, 4 warps x 32 q-rows) ----------------
// 64-row KV tiles, 3-stage single-sync ring, smem 64KB, 2 CTAs/SM.
#define FQ 0
#define FKV 16384
#define FSTAGE 16384
#define FLASH_SMEM (FKV + 3*FSTAGE)   // 65536

__global__ void __launch_bounds__(128, 2)
flash_mma(const f16* __restrict__ qq, const f16* __restrict__ kk,
          const f16* __restrict__ vv,
          const float* __restrict__ Rg,
          const float* __restrict__ avec, const float* __restrict__ cvec,
          f16* __restrict__ aout)
{
    extern __shared__ char smc[];
    uint32_t sb = smem_u32(smc);
    int tid = threadIdx.x, lane = tid & 31, wid = tid >> 5;
    int bid = blockIdx.x;
    int qt = bid & 15, h = (bid >> 4) & 7, b = bid >> 7;
    int bh = b * HH + h;

    float aa = fabsf(avec[h]);
    float ca = fabsf(cvec[h]);

    auto load_kv = [&](int jt, int st) {
        size_t o = ((size_t)bh * NN + jt * 64) * DHH;
        const f16* s2[2] = {kk + o, vv + o};
        uint32_t base = sb + FKV + st * FSTAGE;
        #pragma unroll
        for (int t = 0; t < 2; t++) {
            #pragma unroll
            for (int i = 0; i < 4; i++) {
                int u = tid + i * 128;
                int row = u >> 3, g = u & 7;
                cp16(base + t * 8192 + swz(row * 128 + g * 16),
                     s2[t] + (size_t)row * DHH + g * 8);
            }
        }
        CP_COMMIT();
    };

    // Q tile -> smem (bundled into group 0 with kv0)
    {
        size_t qo = ((size_t)bh * NN + qt * 128) * DHH;
        #pragma unroll
        for (int i = 0; i < 8; i++) {
            int u = tid + i * 128;
            int row = u >> 3, g = u & 7;
            cp16(sb + FQ + swz(row * 128 + g * 16),
                 qq + qo + (size_t)row * DHH + g * 8);
        }
    }
    load_kv(0, 0);
    load_kv(1, 1);

    CP_WAIT1();            // group 0 (Q + KV0) complete
    __syncthreads();

    // hoist Q fragments (32 rows per warp)
    uint32_t qa[4][2][4];
    #pragma unroll
    for (int kt = 0; kt < 4; kt++)
        #pragma unroll
        for (int mt = 0; mt < 2; mt++) {
            uint32_t abyte = swz((wid * 32 + mt * 16 + (lane & 15)) * 128 +
                                 kt * 32 + (lane >> 4) * 16);
            ldsm_x4(qa[kt][mt], sb + FQ + abyte);
        }

    float oacc[2][8][4];
    #pragma unroll
    for (int mt = 0; mt < 2; mt++)
        #pragma unroll
        for (int i = 0; i < 8; i++)
            #pragma unroll
            for (int j = 0; j < 4; j++) oacc[mt][i][j] = 0.f;
    float rsum[2][2] = {{0.f, 0.f}, {0.f, 0.f}};

    for (int jt = 0; jt < 32; jt++) {
        // single barrier per iteration
        if (jt + 1 < 32) { CP_WAIT1(); } else { CP_WAIT0(); }
        __syncthreads();
        // refill the stage consumed two iterations ago ((jt+2)%3 == (jt-1)%3)
        if (jt + 2 < 32) load_kv(jt + 2, (jt + 2) % 3);

        uint32_t bK = sb + FKV + (jt % 3) * FSTAGE;
        uint32_t bV = bK + 8192;

        float rb = Rg[((size_t)b * TT + qt) * TT + (jt >> 1)];
        float dscale = (1.f / (1.f + __expf(aa * rb - ca))) * 0.125f * 1.44269504f;

        #pragma unroll
        for (int c = 0; c < 2; c++) {          // two 32-kv-col chunks
            float sacc[2][4][4];
            #pragma unroll
            for (int mt = 0; mt < 2; mt++)
                #pragma unroll
                for (int i = 0; i < 4; i++)
                    #pragma unroll
                    for (int j = 0; j < 4; j++) sacc[mt][i][j] = 0.f;

            #pragma unroll
            for (int kt = 0; kt < 4; kt++) {
                #pragma unroll
                for (int p = 0; p < 2; p++) {
                    int p16 = c * 2 + p;
                    uint32_t bbyte = swz((p16 * 16 + (lane & 7) + ((lane >> 4) << 3)) * 128 +
                                         kt * 32 + ((lane >> 3) & 1) * 16);
                    uint32_t kb[4];
                    ldsm_x4(kb, bK + bbyte);
                    #pragma unroll
                    for (int mt = 0; mt < 2; mt++)
                        #pragma unroll
                        for (int half = 0; half < 2; half++)
                            mma16816(sacc[mt][p * 2 + half], qa[kt][mt], &kb[half * 2]);
                }
            }

            // softmax numerator (bounded logits)
            #pragma unroll
            for (int mt = 0; mt < 2; mt++)
                #pragma unroll
                for (int nt = 0; nt < 4; nt++)
                    #pragma unroll
                    for (int r = 0; r < 4; r++) {
                        float p = ex2f(fmaxf(sacc[mt][nt][r], 0.f) * dscale);
                        sacc[mt][nt][r] = p;
                        rsum[mt][r >> 1] += p;
                    }

            // pack P fragments
            uint32_t pa[2][2][4];
            #pragma unroll
            for (int mt = 0; mt < 2; mt++)
                #pragma unroll
                for (int g = 0; g < 2; g++) {
                    pa[mt][g][0] = pack2h(sacc[mt][2*g][0],   sacc[mt][2*g][1]);
                    pa[mt][g][1] = pack2h(sacc[mt][2*g][2],   sacc[mt][2*g][3]);
                    pa[mt][g][2] = pack2h(sacc[mt][2*g+1][0], sacc[mt][2*g+1][1]);
                    pa[mt][g][3] = pack2h(sacc[mt][2*g+1][2], sacc[mt][2*g+1][3]);
                }

            // O += P(32x32) @ V(32x64)
            #pragma unroll
            for (int g = 0; g < 2; g++) {
                int vrow = c * 32 + g * 16;
                #pragma unroll
                for (int p = 0; p < 4; p++) {
                    uint32_t vbyte = swz((vrow + (lane & 7) + ((lane >> 3) & 1) * 8) * 128 +
                                         p * 32 + (lane >> 4) * 16);
                    uint32_t vb[4];
                    ldsm_x4t(vb, bV + vbyte);
                    #pragma unroll
                    for (int mt = 0; mt < 2; mt++)
                        #pragma unroll
                        for (int half = 0; half < 2; half++)
                            mma16816(oacc[mt][p * 2 + half], pa[mt][g], &vb[half * 2]);
                }
            }
        }
        // no bottom barrier
    }

    // reduce row-sums across the quad
    #pragma unroll
    for (int mt = 0; mt < 2; mt++)
        #pragma unroll
        for (int hh = 0; hh < 2; hh++) {
            rsum[mt][hh] += __shfl_xor_sync(0xffffffffu, rsum[mt][hh], 1);
            rsum[mt][hh] += __shfl_xor_sync(0xffffffffu, rsum[mt][hh], 2);
        }

    // epilogue
    int r0 = qt * 128 + wid * 32 + (lane >> 2);
    f16* ob = aout + ((size_t)b * NN + r0) * DIMM + h * DHH;
    #pragma unroll
    for (int mt = 0; mt < 2; mt++) {
        float inv_lo = 1.f / rsum[mt][0], inv_hi = 1.f / rsum[mt][1];
        f16* om = ob + (size_t)(mt * 16) * DIMM;
        #pragma unroll
        for (int nt = 0; nt < 8; nt++) {
            int c = nt * 8 + 2 * (lane & 3);
            *(uint32_t*)(om + c) =
                pack2h(oacc[mt][nt][0] * inv_lo, oacc[mt][nt][1] * inv_lo);
            *(uint32_t*)(om + (size_t)8 * DIMM + c) =
                pack2h(oacc[mt][nt][2] * inv_hi, oacc[mt][nt][3] * inv_hi);
        }
    }
}

// ---------------- launch ----------------
extern "C" void kernel_launch(void* const* d_in, const int* in_sizes, int n_in,
                              void* d_out, int out_size)
{
    const float* x     = (const float*)d_in[0];
    const float* R     = (const float*)d_in[1];
    const float* gamma = (const float*)d_in[2];
    const float* beta  = (const float*)d_in[3];
    const float* Wqkv  = (const float*)d_in[4];
    const float* Wout  = (const float*)d_in[5];
    const float* av    = (const float*)d_in[6];
    const float* cv    = (const float*)d_in[7];
    float* out = (float*)d_out;

    f16 *xn, *wq, *wo, *qq, *kk, *vv, *aa;
    cudaGetSymbolAddress((void**)&xn, g_xn);
    cudaGetSymbolAddress((void**)&wq, g_wq);   cudaGetSymbolAddress((void**)&wo, g_wo);
    cudaGetSymbolAddress((void**)&qq, g_q);    cudaGetSymbolAddress((void**)&kk, g_k);
    cudaGetSymbolAddress((void**)&vv, g_v);    cudaGetSymbolAddress((void**)&aa, g_a);

    cudaFuncSetAttribute((const void*)mma_gemm<true>,
                         cudaFuncAttributeMaxDynamicSharedMemorySize, GEMM_SMEM);
    cudaFuncSetAttribute((const void*)mma_gemm<false>,
                         cudaFuncAttributeMaxDynamicSharedMemorySize, GEMM_SMEM);
    cudaFuncSetAttribute((const void*)flash_mma,
                         cudaFuncAttributeMaxDynamicSharedMemorySize, FLASH_SMEM);

    // 1) fused prep: warp-per-row LN + weight transposes
    int prep_blocks = LN_BLOCKS + (QKVN / 32) * (DIMM / 32) + (DIMM / 32) * (DIMM / 32);
    prep_kernel<<<prep_blocks, 256>>>(x, gamma, beta, Wqkv, Wout, xn);

    // 2) QKV projection (grid 12x64, 2 CTAs/SM, 2-stage)
    mma_gemm<true><<<dim3(QKVN / 128, ROWS / 128), 256, GEMM_SMEM>>>(
        xn, wq, nullptr, QKVN, DIMM, qq, kk, vv);

    // 3) flash attention (64-row KV tiles, 3-stage single-sync ring)
    flash_mma<<<BB * HH * 16, 128, FLASH_SMEM>>>(qq, kk, vv, R, av, cv, aa);

    // 4) output projection (grid 4x64, 2 CTAs/SM, 2-stage)
    mma_gemm<false><<<dim3(DIMM / 128, ROWS / 128), 256, GEMM_SMEM>>>(
        aa, wo, out, DIMM, DIMM, nullptr, nullptr, nullptr);
}